// round 4
// baseline (speedup 1.0000x reference)
#include <cuda_runtime.h>
#include <cstdint>

// ---------------------------------------------------------------------------
// out[b,c] = sum_e y[b,e]*( sum_{w<=v<=i} S3[c,e,(w,v,i)] x_w x_v x_i
//                         + sum_{w<=v}    S2[c,e,(w,v)]   x_w x_v
//                         + sum_w         V1[c,e,w]       x_w )
// Round 4: parallel k_tab, fused precompute, length-sorted pair chunks (2
// pairs share one y load), (s2,0)-packed d-init, conflict-free k_s3.
// ---------------------------------------------------------------------------

namespace {
constexpr int LDIM = 16;
constexpr int EDIM = 10;
constexpr int CDIM = 256;
constexpr int BDIM = 1024;
constexpr int K3C  = 23;
constexpr int K2C  = 4;

constexpr int NPAIR    = 136;           // (w<=v) pairs, 8 buckets x 17
constexpr int NBUCK    = 8;
constexpr int PPB      = 17;            // pairs per bucket
constexpr int BSTRIDE  = 64;            // ull slots per bucket stream (max 63 used)
constexpr int NSLOT_U  = NBUCK * BSTRIDE;   // 512 ull per e
constexpr int NSLOT_F  = 2 * NSLOT_U;       // 1024 floats per e

constexpr int S3_PER_C  = EDIM * NSLOT_F;   // 10240 floats
constexpr int S2U_PER_C = EDIM * NPAIR;     // 1360 ull
constexpr int V1_PER_C  = EDIM * LDIM;      // 160

// sc_main smem (bytes)
constexpr int SMEM_MAIN =
    S3_PER_C * 4 +        // 40960 S3 streams
    S2U_PER_C * 8 +       // 10880 (s2,0) packed
    256 * 17 * 4 +        // 17408 x scalars, stride 17
    EDIM * 256 * 8 +      // 20480 dup'd y pairs [e][b]
    NPAIR * 4 * 4 +       //  2176 tables (w,v,off,len)
    8 * 256 * 4;          //  8192 reduction
// = 100096

constexpr int SMEM_KS3 = (K3C * NSLOT_F + EDIM * K3C + 8) * 4;  // ~95.2 KB
}

// ---- device scratch ----------------------------------------------------------
__device__ int   g_pw[NPAIR], g_pv[NPAIR], g_off[NPAIR], g_len[NPAIR];
__device__ int   g_s2p[NSLOT_F], g_s2i[NSLOT_F];   // float-slot -> pair, i
__device__ float U3symT[K3C * NSLOT_F];            // [k][slot], zero-padded
__device__ float S3g[CDIM * S3_PER_C];             // ~10.5 MB
__device__ unsigned long long S2gu[CDIM * S2U_PER_C];
__device__ float V1g[CDIM * V1_PER_C];

// ---- packed f32x2 helpers (sm_103a) -------------------------------------------
using ull = unsigned long long;
__device__ __forceinline__ ull pk2(float a, float b) {
    ull r;
    asm("mov.b64 %0, {%1, %2};"
        : "=l"(r) : "r"(__float_as_uint(a)), "r"(__float_as_uint(b)));
    return r;
}
__device__ __forceinline__ ull fma2(ull a, ull b, ull c) {
    ull d;
    asm("fma.rn.f32x2 %0, %1, %2, %3;" : "=l"(d) : "l"(a), "l"(b), "l"(c));
    return d;
}
__device__ __forceinline__ void upk2(ull v, float& a, float& b) {
    unsigned int lo, hi;
    asm("mov.b64 {%0, %1}, %2;" : "=r"(lo), "=r"(hi) : "l"(v));
    a = __uint_as_float(lo);
    b = __uint_as_float(hi);
}

// ---- k_tab: fully parallel table builder --------------------------------------
// Pairs sorted by len8 desc (counting-sort rank, closed form), round-robin into
// 8 buckets of 17. Chunk (2j,2j+1): both alloc len(2j) slots (sorted => pad<=1).
// Leftover j=16 is always len 1. cnt(L) = 4*(8-L)+3; lens by rank:
// 0-2:8, 3-9:7, 10-20:6, 21-35:5, 36-54:4, 55-77:3, 78-104:2, 105-135:1.
__device__ __forceinline__ int len_of_rank(int r) {
    int o = 0, L = 8;
    while (L > 1 && o + 4 * (8 - L) + 3 <= r) { o += 4 * (8 - L) + 3; L--; }
    return L;
}
__global__ void k_tab() {
    const int tid = threadIdx.x;
    for (int s = tid; s < NSLOT_F; s += 256) { g_s2i[s] = -1; g_s2p[s] = 0; }
    __syncthreads();
    if (tid >= NPAIR) return;

    // decode tid -> (w,v), w-major original order
    int p = tid, w = 0;
    while (p >= LDIM - w) { p -= LDIM - w; w++; }
    const int v = w + p;
    const int g = v >> 1;
    const int L = 8 - g;

    // rank among same-len pairs (original order)
    int idx = 0;
    for (int w2 = 0; w2 < w; w2++) {
        if (2 * g     >= w2) idx++;
        if (2 * g + 1 >= w2) idx++;
    }
    if ((v & 1) && (2 * g >= w)) idx++;
    int offL = 0;
    for (int L2 = 8; L2 > L; L2--) offL += 4 * (8 - L2) + 3;
    const int rank   = offL + idx;
    const int bucket = rank & 7;
    const int j      = rank >> 3;

    // local offset: full chunks before + half-chunk if odd j
    int off_local = 0;
    for (int cj = 0; cj < (j >> 1); cj++)
        off_local += 2 * len_of_rank((2 * cj) * 8 + bucket);
    if (j & 1)
        off_local += len_of_rank((j - 1) * 8 + bucket);

    const int off_abs = bucket * BSTRIDE + off_local;
    const int pi = bucket * PPB + j;
    g_pw[pi]  = w;
    g_pv[pi]  = v;
    g_off[pi] = off_abs;
    g_len[pi] = L;

    for (int u = 0; u < L; u++)
        for (int r = 0; r < 2; r++) {
            const int s = 2 * (off_abs + u) + r;
            const int i = 14 - 2 * u + r;
            g_s2p[s] = pi;
            g_s2i[s] = (i >= v) ? i : -1;
        }
}

// ---- k_sym: symmetrized U3, transposed [k][slot] ------------------------------
__device__ __forceinline__ float u3at(const float* U3, int a, int b, int c, int k) {
    return U3[((a * 16 + b) * 16 + c) * K3C + k];
}
__global__ void k_sym(const float* __restrict__ U3) {
    const int idx = blockIdx.x * 256 + threadIdx.x;   // 23 * 1024 = 23552
    if (idx >= K3C * NSLOT_F) return;
    const int s = idx & (NSLOT_F - 1);
    const int k = idx >> 10;
    const int i = g_s2i[s];
    float val = 0.f;
    if (i >= 0) {
        const int pi = g_s2p[s];
        const int w = g_pw[pi], v = g_pv[pi];
        if (w == v && v == i) {
            val = u3at(U3, w, w, w, k);
        } else if (w == v) {
            val = u3at(U3, w, w, i, k) + u3at(U3, w, i, w, k) + u3at(U3, i, w, w, k);
        } else if (v == i) {
            val = u3at(U3, w, v, v, k) + u3at(U3, v, w, v, k) + u3at(U3, v, v, w, k);
        } else {
            val = u3at(U3, w, v, i, k) + u3at(U3, w, i, v, k) +
                  u3at(U3, v, w, i, k) + u3at(U3, v, i, w, k) +
                  u3at(U3, i, w, v, k) + u3at(U3, i, v, w, k);
        }
    }
    U3symT[k * NSLOT_F + s] = val;
}

// ---- k_s3: per-c contraction + fused S2/V1 ------------------------------------
__global__ __launch_bounds__(512, 1)
void k_s3(const float* __restrict__ W3, const float* __restrict__ U2,
          const float* __restrict__ W2, const float* __restrict__ U1,
          const float* __restrict__ W1) {
    extern __shared__ float sm[];
    float* sU = sm;                       // [23][1024]
    float* sW = sm + K3C * NSLOT_F;       // [10][23]
    const int tid = threadIdx.x;
    const int c   = blockIdx.x;

    for (int t = tid; t < K3C * NSLOT_F; t += 512) sU[t] = U3symT[t];
    if (tid < EDIM * K3C) {
        const int e = tid / K3C, k = tid - e * K3C;
        sW[tid] = W3[(e * K3C + k) * CDIM + c];
    }
    __syncthreads();

#pragma unroll 1
    for (int idx = tid; idx < S3_PER_C; idx += 512) {
        const int e = idx >> 10;
        const int s = idx & (NSLOT_F - 1);
        float a = 0.f;
#pragma unroll
        for (int k = 0; k < K3C; k++)
            a = fmaf(sU[k * NSLOT_F + s], sW[e * K3C + k], a);
        S3g[c * S3_PER_C + idx] = a;
    }

    // S2 packed (s2, 0)
    for (int t = tid; t < S2U_PER_C; t += 512) {
        const int e = t / NPAIR, pp = t - e * NPAIR;
        const int w = g_pw[pp], v = g_pv[pp];
        float s = 0.f;
#pragma unroll
        for (int k = 0; k < K2C; k++) {
            float u = U2[(w * 16 + v) * K2C + k];
            if (w != v) u += U2[(v * 16 + w) * K2C + k];
            s = fmaf(u, W2[(e * K2C + k) * CDIM + c], s);
        }
        S2gu[c * S2U_PER_C + t] = (ull)__float_as_uint(s);  // (s, 0)
    }
    // V1
    if (tid < V1_PER_C) {
        const int e = tid >> 4, w = tid & 15;
        V1g[c * V1_PER_C + tid] = U1[w] * W1[e * CDIM + c];
    }
}

// ---- sc_main dot kernels -------------------------------------------------------
// Chunk of 2 pairs, both padded to N slots (streams adjacent: stB = stA + N).
// One y load per (chunk, e) shared by both folds.
template <int N>
__device__ __forceinline__ void dot2(
    const ull* __restrict__ st0, const ull* __restrict__ s2A,
    const ull* __restrict__ s2B, const ull* __restrict__ yrow0, int bg,
    const ull (&xp0)[8], const ull (&xp1)[8], const ull (&xp2)[8], const ull (&xp3)[8],
    ull& yaA0, ull& yaA1, ull& yaA2, ull& yaA3,
    ull& yaB0, ull& yaB1, ull& yaB2, ull& yaB3)
{
#pragma unroll 1
    for (int e = 0; e < EDIM; e++) {
        const ull* st = st0 + e * NSLOT_U;
        const ull y0 = yrow0[e * 256 + bg];
        const ull y1 = yrow0[e * 256 + bg + 64];
        const ull y2 = yrow0[e * 256 + bg + 128];
        const ull y3 = yrow0[e * 256 + bg + 192];
        {
            const ull s2 = s2A[e * NPAIR];
            ull d0 = s2, d1 = s2, d2 = s2, d3 = s2;
#pragma unroll
            for (int u = N - 1; u >= 0; u--) {
                const ull t = st[u];
                d0 = fma2(t, xp0[7 - u], d0);
                d1 = fma2(t, xp1[7 - u], d1);
                d2 = fma2(t, xp2[7 - u], d2);
                d3 = fma2(t, xp3[7 - u], d3);
            }
            yaA0 = fma2(d0, y0, yaA0);
            yaA1 = fma2(d1, y1, yaA1);
            yaA2 = fma2(d2, y2, yaA2);
            yaA3 = fma2(d3, y3, yaA3);
        }
        {
            const ull s2 = s2B[e * NPAIR];
            ull d0 = s2, d1 = s2, d2 = s2, d3 = s2;
#pragma unroll
            for (int u = N - 1; u >= 0; u--) {
                const ull t = st[N + u];
                d0 = fma2(t, xp0[7 - u], d0);
                d1 = fma2(t, xp1[7 - u], d1);
                d2 = fma2(t, xp2[7 - u], d2);
                d3 = fma2(t, xp3[7 - u], d3);
            }
            yaB0 = fma2(d0, y0, yaB0);
            yaB1 = fma2(d1, y1, yaB1);
            yaB2 = fma2(d2, y2, yaB2);
            yaB3 = fma2(d3, y3, yaB3);
        }
    }
}

// Grid (c=256, btile=4). 512 threads: bg = tid&63 owns 4 b's; psplit = tid>>6
// owns one bucket of 17 len-sorted pairs. Lanes carry (even-i, odd-i).
__global__ __launch_bounds__(512, 1)
void sc_main(const float* __restrict__ x, const float* __restrict__ y,
             float* __restrict__ out) {
    extern __shared__ char smraw[];
    float* sS3 = reinterpret_cast<float*>(smraw);
    ull*   sS2 = reinterpret_cast<ull*>(sS3 + S3_PER_C);
    float* sXs = reinterpret_cast<float*>(sS2 + S2U_PER_C);
    ull*   sYd = reinterpret_cast<ull*>(sXs + 256 * 17);
    int*   sPW = reinterpret_cast<int*>(sYd + EDIM * 256);
    int*   sPV = sPW + NPAIR;
    int*   sOF = sPV + NPAIR;
    int*   sLN = sOF + NPAIR;
    float* red = reinterpret_cast<float*>(sLN + NPAIR);
    const ull* sS3u = reinterpret_cast<const ull*>(sS3);

    const int tid    = threadIdx.x;
    const int c      = blockIdx.x;
    const int base   = blockIdx.y * 256;
    const int bg     = tid & 63;
    const int psplit = tid >> 6;

    // ---- stage S3 / S2 ----
    {
        const float4* src = reinterpret_cast<const float4*>(S3g + c * S3_PER_C);
        float4* dst = reinterpret_cast<float4*>(sS3);
#pragma unroll
        for (int t = 0; t < S3_PER_C / 4 / 512; t++)
            dst[tid + t * 512] = src[tid + t * 512];
        for (int t = tid; t < S2U_PER_C; t += 512)
            sS2[t] = S2gu[c * S2U_PER_C + t];
    }
    // ---- stage x scalars ----
#pragma unroll
    for (int t = 0; t < 8; t++) {
        const int idx = tid + t * 512;            // 4096 = 256*16
        const int b = idx >> 4, i = idx & 15;
        sXs[b * 17 + i] = x[((base + b) * CDIM + c) * LDIM + i];
    }
    // ---- stage dup'd y pairs [e][b] ----
#pragma unroll
    for (int t = 0; t < 5; t++) {
        const int idx = tid + t * 512;            // 2560 = 10*256
        const int b = idx & 255, e = idx >> 8;
        const float yv = y[(base + b) * EDIM + e];
        sYd[e * 256 + b] = pk2(yv, yv);
    }
    if (tid < NPAIR) {
        sPW[tid] = g_pw[tid];
        sPV[tid] = g_pv[tid];
        sOF[tid] = g_off[tid];
        sLN[tid] = g_len[tid];
    }
    __syncthreads();

    // ---- per-thread packed x (4 b's) ----
    const int b0 = bg, b1 = bg + 64, b2 = bg + 128, b3 = bg + 192;
    ull xp0[8], xp1[8], xp2[8], xp3[8];
#pragma unroll
    for (int q = 0; q < 8; q++) {
        xp0[q] = pk2(sXs[b0 * 17 + 2 * q], sXs[b0 * 17 + 2 * q + 1]);
        xp1[q] = pk2(sXs[b1 * 17 + 2 * q], sXs[b1 * 17 + 2 * q + 1]);
        xp2[q] = pk2(sXs[b2 * 17 + 2 * q], sXs[b2 * 17 + 2 * q + 1]);
        xp3[q] = pk2(sXs[b3 * 17 + 2 * q], sXs[b3 * 17 + 2 * q + 1]);
    }

    ull acc0 = 0ull, acc1 = 0ull, acc2 = 0ull, acc3 = 0ull;

#pragma unroll 1
    for (int cj = 0; cj < 8; cj++) {
        const int pA = psplit * PPB + 2 * cj;
        const int pB = pA + 1;
        const int wA = sPW[pA], vA = sPV[pA];
        const int wB = sPW[pB], vB = sPV[pB];
        const int off = sOF[pA];
        const int N   = sLN[pA];
        const float PA0 = sXs[b0 * 17 + wA] * sXs[b0 * 17 + vA];
        const float PA1 = sXs[b1 * 17 + wA] * sXs[b1 * 17 + vA];
        const float PA2 = sXs[b2 * 17 + wA] * sXs[b2 * 17 + vA];
        const float PA3 = sXs[b3 * 17 + wA] * sXs[b3 * 17 + vA];
        const float PB0 = sXs[b0 * 17 + wB] * sXs[b0 * 17 + vB];
        const float PB1 = sXs[b1 * 17 + wB] * sXs[b1 * 17 + vB];
        const float PB2 = sXs[b2 * 17 + wB] * sXs[b2 * 17 + vB];
        const float PB3 = sXs[b3 * 17 + wB] * sXs[b3 * 17 + vB];

        ull yaA0 = 0ull, yaA1 = 0ull, yaA2 = 0ull, yaA3 = 0ull;
        ull yaB0 = 0ull, yaB1 = 0ull, yaB2 = 0ull, yaB3 = 0ull;
        const ull* st0 = sS3u + off;
        const ull* s2A = sS2 + pA;
        const ull* s2B = sS2 + pB;
        switch (N) {
            case 8: dot2<8>(st0, s2A, s2B, sYd, bg, xp0, xp1, xp2, xp3,
                            yaA0, yaA1, yaA2, yaA3, yaB0, yaB1, yaB2, yaB3); break;
            case 7: dot2<7>(st0, s2A, s2B, sYd, bg, xp0, xp1, xp2, xp3,
                            yaA0, yaA1, yaA2, yaA3, yaB0, yaB1, yaB2, yaB3); break;
            case 6: dot2<6>(st0, s2A, s2B, sYd, bg, xp0, xp1, xp2, xp3,
                            yaA0, yaA1, yaA2, yaA3, yaB0, yaB1, yaB2, yaB3); break;
            case 5: dot2<5>(st0, s2A, s2B, sYd, bg, xp0, xp1, xp2, xp3,
                            yaA0, yaA1, yaA2, yaA3, yaB0, yaB1, yaB2, yaB3); break;
            case 4: dot2<4>(st0, s2A, s2B, sYd, bg, xp0, xp1, xp2, xp3,
                            yaA0, yaA1, yaA2, yaA3, yaB0, yaB1, yaB2, yaB3); break;
            case 3: dot2<3>(st0, s2A, s2B, sYd, bg, xp0, xp1, xp2, xp3,
                            yaA0, yaA1, yaA2, yaA3, yaB0, yaB1, yaB2, yaB3); break;
            case 2: dot2<2>(st0, s2A, s2B, sYd, bg, xp0, xp1, xp2, xp3,
                            yaA0, yaA1, yaA2, yaA3, yaB0, yaB1, yaB2, yaB3); break;
            default: dot2<1>(st0, s2A, s2B, sYd, bg, xp0, xp1, xp2, xp3,
                             yaA0, yaA1, yaA2, yaA3, yaB0, yaB1, yaB2, yaB3); break;
        }
        acc0 = fma2(pk2(PA0, PA0), yaA0, acc0);
        acc1 = fma2(pk2(PA1, PA1), yaA1, acc1);
        acc2 = fma2(pk2(PA2, PA2), yaA2, acc2);
        acc3 = fma2(pk2(PA3, PA3), yaA3, acc3);
        acc0 = fma2(pk2(PB0, PB0), yaB0, acc0);
        acc1 = fma2(pk2(PB1, PB1), yaB1, acc1);
        acc2 = fma2(pk2(PB2, PB2), yaB2, acc2);
        acc3 = fma2(pk2(PB3, PB3), yaB3, acc3);
    }

    // ---- leftover pair (j=16): always len 1 ----
    {
        const int p = psplit * PPB + 16;
        const int w = sPW[p], v = sPV[p];
        const int off = sOF[p];
        const float P0 = sXs[b0 * 17 + w] * sXs[b0 * 17 + v];
        const float P1 = sXs[b1 * 17 + w] * sXs[b1 * 17 + v];
        const float P2 = sXs[b2 * 17 + w] * sXs[b2 * 17 + v];
        const float P3 = sXs[b3 * 17 + w] * sXs[b3 * 17 + v];
        ull ya0 = 0ull, ya1 = 0ull, ya2 = 0ull, ya3 = 0ull;
#pragma unroll 1
        for (int e = 0; e < EDIM; e++) {
            const ull t  = sS3u[e * NSLOT_U + off];
            const ull s2 = sS2[e * NPAIR + p];
            const ull d0 = fma2(t, xp0[7], s2);
            const ull d1 = fma2(t, xp1[7], s2);
            const ull d2 = fma2(t, xp2[7], s2);
            const ull d3 = fma2(t, xp3[7], s2);
            ya0 = fma2(d0, sYd[e * 256 + bg], ya0);
            ya1 = fma2(d1, sYd[e * 256 + bg + 64], ya1);
            ya2 = fma2(d2, sYd[e * 256 + bg + 128], ya2);
            ya3 = fma2(d3, sYd[e * 256 + bg + 192], ya3);
        }
        acc0 = fma2(pk2(P0, P0), ya0, acc0);
        acc1 = fma2(pk2(P1, P1), ya1, acc1);
        acc2 = fma2(pk2(P2, P2), ya2, acc2);
        acc3 = fma2(pk2(P3, P3), ya3, acc3);
    }

    float lo, hi;
    float s0, s1, s2v, s3v;
    upk2(acc0, lo, hi); s0  = lo + hi;
    upk2(acc1, lo, hi); s1  = lo + hi;
    upk2(acc2, lo, hi); s2v = lo + hi;
    upk2(acc3, lo, hi); s3v = lo + hi;

    // ---- nu=1 (psplit 0 only) ----
    if (psplit == 0) {
        const float* v1 = V1g + c * V1_PER_C;
        float add0 = 0.f, add1 = 0.f, add2 = 0.f, add3 = 0.f;
#pragma unroll 1
        for (int e = 0; e < EDIM; e++) {
            float t0 = 0.f, t1 = 0.f, t2 = 0.f, t3 = 0.f;
#pragma unroll
            for (int w = 0; w < 16; w++) {
                const float vv = v1[e * 16 + w];
                t0 = fmaf(vv, sXs[b0 * 17 + w], t0);
                t1 = fmaf(vv, sXs[b1 * 17 + w], t1);
                t2 = fmaf(vv, sXs[b2 * 17 + w], t2);
                t3 = fmaf(vv, sXs[b3 * 17 + w], t3);
            }
            add0 = fmaf(y[(base + b0) * EDIM + e], t0, add0);
            add1 = fmaf(y[(base + b1) * EDIM + e], t1, add1);
            add2 = fmaf(y[(base + b2) * EDIM + e], t2, add2);
            add3 = fmaf(y[(base + b3) * EDIM + e], t3, add3);
        }
        s0 += add0; s1 += add1; s2v += add2; s3v += add3;
    }

    // ---- deterministic cross-split reduction ----
    red[psplit * 256 + b0] = s0;
    red[psplit * 256 + b1] = s1;
    red[psplit * 256 + b2] = s2v;
    red[psplit * 256 + b3] = s3v;
    __syncthreads();
    if (tid < 256) {
        float s = 0.f;
#pragma unroll
        for (int k = 0; k < 8; k++) s += red[k * 256 + tid];
        out[(base + tid) * CDIM + c] = s;
    }
}

// ---- launch --------------------------------------------------------------------
extern "C" void kernel_launch(void* const* d_in, const int* in_sizes, int n_in,
                              void* d_out, int out_size) {
    const float* x  = (const float*)d_in[0];
    const float* y  = (const float*)d_in[1];
    const float* U3 = (const float*)d_in[2];
    const float* U2 = (const float*)d_in[3];
    const float* U1 = (const float*)d_in[4];
    const float* W3 = (const float*)d_in[5];
    const float* W2 = (const float*)d_in[6];
    const float* W1 = (const float*)d_in[7];
    float* out = (float*)d_out;

    cudaFuncSetAttribute(k_s3, cudaFuncAttributeMaxDynamicSharedMemorySize, SMEM_KS3);
    cudaFuncSetAttribute(sc_main, cudaFuncAttributeMaxDynamicSharedMemorySize, SMEM_MAIN);

    k_tab<<<1, 256>>>();
    k_sym<<<(K3C * NSLOT_F + 255) / 256, 256>>>(U3);
    k_s3<<<CDIM, 512, SMEM_KS3>>>(W3, U2, W2, U1, W1);

    dim3 grid(CDIM, BDIM / 256);
    sc_main<<<grid, 512, SMEM_MAIN>>>(x, y, out);
}

// round 5
// speedup vs baseline: 1.5218x; 1.5218x over previous
#include <cuda_runtime.h>
#include <cstdint>

// ---------------------------------------------------------------------------
// out[b,c] = sum_e y[b,e]*( sum_{w<=v<=i} S3[c,e,(w,v,i)] x_w x_v x_i
//                         + sum_{w<=v}    S2[c,e,(w,v)]   x_w x_v
//                         + sum_w         V1[c,e,w]       x_w )
// Round 5: round-3 single-pair dot (90-reg codegen) + balanced length-sorted
// buckets + round-4 parallel/fused precompute.
// ---------------------------------------------------------------------------

namespace {
constexpr int LDIM = 16;
constexpr int EDIM = 10;
constexpr int CDIM = 256;
constexpr int BDIM = 1024;
constexpr int K3C  = 23;
constexpr int K2C  = 4;

constexpr int NPAIR    = 136;           // (w<=v) pairs, 8 buckets x 17
constexpr int NBUCK    = 8;
constexpr int PPB      = 17;
constexpr int BSTRIDE  = 64;            // ull slots per bucket (max 59 used)
constexpr int NSLOT_U  = NBUCK * BSTRIDE;   // 512 ull per e
constexpr int NSLOT_F  = 2 * NSLOT_U;       // 1024 floats per e

constexpr int S3_PER_C  = EDIM * NSLOT_F;   // 10240 floats
constexpr int S2U_PER_C = EDIM * NPAIR;     // 1360 ull
constexpr int V1_PER_C  = EDIM * LDIM;      // 160

constexpr int SMEM_MAIN =
    S3_PER_C * 4 +        // 40960
    S2U_PER_C * 8 +       // 10880
    256 * 17 * 4 +        // 17408 x scalars, stride 17
    EDIM * 256 * 8 +      // 20480 dup'd y pairs [e][b]
    NPAIR * 4 * 4 +       //  2176 tables (w,v,off,len)
    8 * 256 * 4;          //  8192 reduction
// = 100096

constexpr int SMEM_KS3 = (K3C * NSLOT_F + EDIM * K3C + 8) * 4;  // ~95.2 KB
}

// ---- device scratch ----------------------------------------------------------
__device__ int   g_pw[NPAIR], g_pv[NPAIR], g_off[NPAIR], g_len[NPAIR];
__device__ int   g_s2p[NSLOT_F], g_s2i[NSLOT_F];   // float-slot -> pair, i
__device__ float U3symT[K3C * NSLOT_F];            // [k][slot], zero-padded
__device__ float S3g[CDIM * S3_PER_C];             // ~10.5 MB
__device__ unsigned long long S2gu[CDIM * S2U_PER_C];
__device__ float V1g[CDIM * V1_PER_C];

// ---- packed f32x2 helpers (sm_103a) -------------------------------------------
using ull = unsigned long long;
__device__ __forceinline__ ull pk2(float a, float b) {
    ull r;
    asm("mov.b64 %0, {%1, %2};"
        : "=l"(r) : "r"(__float_as_uint(a)), "r"(__float_as_uint(b)));
    return r;
}
__device__ __forceinline__ ull fma2(ull a, ull b, ull c) {
    ull d;
    asm("fma.rn.f32x2 %0, %1, %2, %3;" : "=l"(d) : "l"(a), "l"(b), "l"(c));
    return d;
}
__device__ __forceinline__ void upk2(ull v, float& a, float& b) {
    unsigned int lo, hi;
    asm("mov.b64 {%0, %1}, %2;" : "=r"(lo), "=r"(hi) : "l"(v));
    a = __uint_as_float(lo);
    b = __uint_as_float(hi);
}

// ---- k_tab: parallel table builder, balanced buckets, NO padding --------------
// Pairs ranked by len desc; rank r -> bucket r&7, slot j = r>>3.
// cnt(L) = 4*(8-L)+3:  len8 r0-2, len7 r3-9, len6 r10-20, len5 r21-35,
// len4 r36-54, len3 r55-77, len2 r78-104, len1 r105-135.
__device__ __forceinline__ int len_of_rank(int r) {
    int o = 0, L = 8;
    while (L > 1 && o + 4 * (8 - L) + 3 <= r) { o += 4 * (8 - L) + 3; L--; }
    return L;
}
__global__ void k_tab() {
    const int tid = threadIdx.x;
    for (int s = tid; s < NSLOT_F; s += 256) { g_s2i[s] = -1; g_s2p[s] = 0; }
    __syncthreads();
    if (tid >= NPAIR) return;

    // decode tid -> (w,v), w-major original order
    int p = tid, w = 0;
    while (p >= LDIM - w) { p -= LDIM - w; w++; }
    const int v = w + p;
    const int g = v >> 1;
    const int L = 8 - g;

    // rank among same-len pairs (original order within the len class)
    int idx = 0;
    for (int w2 = 0; w2 < w; w2++) {
        if (2 * g     >= w2) idx++;
        if (2 * g + 1 >= w2) idx++;
    }
    if ((v & 1) && (2 * g >= w)) idx++;
    int offL = 0;
    for (int L2 = 8; L2 > L; L2--) offL += 4 * (8 - L2) + 3;
    const int rank   = offL + idx;
    const int bucket = rank & 7;
    const int j      = rank >> 3;

    // exact-length packing: offset = sum of lens of earlier slots in bucket
    int off_local = 0;
    for (int j2 = 0; j2 < j; j2++)
        off_local += len_of_rank(j2 * 8 + bucket);

    const int off_abs = bucket * BSTRIDE + off_local;
    const int pi = bucket * PPB + j;
    g_pw[pi]  = w;
    g_pv[pi]  = v;
    g_off[pi] = off_abs;
    g_len[pi] = L;

    for (int u = 0; u < L; u++)
        for (int r = 0; r < 2; r++) {
            const int s = 2 * (off_abs + u) + r;
            const int i = 14 - 2 * u + r;
            g_s2p[s] = pi;
            g_s2i[s] = (i >= v) ? i : -1;
        }
}

// ---- k_sym: symmetrized U3, transposed [k][slot] ------------------------------
__device__ __forceinline__ float u3at(const float* U3, int a, int b, int c, int k) {
    return U3[((a * 16 + b) * 16 + c) * K3C + k];
}
__global__ void k_sym(const float* __restrict__ U3) {
    const int idx = blockIdx.x * 256 + threadIdx.x;   // 23 * 1024
    if (idx >= K3C * NSLOT_F) return;
    const int s = idx & (NSLOT_F - 1);
    const int k = idx >> 10;
    const int i = g_s2i[s];
    float val = 0.f;
    if (i >= 0) {
        const int pi = g_s2p[s];
        const int w = g_pw[pi], v = g_pv[pi];
        if (w == v && v == i) {
            val = u3at(U3, w, w, w, k);
        } else if (w == v) {
            val = u3at(U3, w, w, i, k) + u3at(U3, w, i, w, k) + u3at(U3, i, w, w, k);
        } else if (v == i) {
            val = u3at(U3, w, v, v, k) + u3at(U3, v, w, v, k) + u3at(U3, v, v, w, k);
        } else {
            val = u3at(U3, w, v, i, k) + u3at(U3, w, i, v, k) +
                  u3at(U3, v, w, i, k) + u3at(U3, v, i, w, k) +
                  u3at(U3, i, w, v, k) + u3at(U3, i, v, w, k);
        }
    }
    U3symT[k * NSLOT_F + s] = val;
}

// ---- k_s3: per-c contraction + fused S2/V1 ------------------------------------
__global__ __launch_bounds__(512, 1)
void k_s3(const float* __restrict__ W3, const float* __restrict__ U2,
          const float* __restrict__ W2, const float* __restrict__ U1,
          const float* __restrict__ W1) {
    extern __shared__ float sm[];
    float* sU = sm;                       // [23][1024]
    float* sW = sm + K3C * NSLOT_F;       // [10][23]
    const int tid = threadIdx.x;
    const int c   = blockIdx.x;

    for (int t = tid; t < K3C * NSLOT_F; t += 512) sU[t] = U3symT[t];
    if (tid < EDIM * K3C) {
        const int e = tid / K3C, k = tid - e * K3C;
        sW[tid] = W3[(e * K3C + k) * CDIM + c];
    }
    __syncthreads();

#pragma unroll 1
    for (int idx = tid; idx < S3_PER_C; idx += 512) {
        const int e = idx >> 10;
        const int s = idx & (NSLOT_F - 1);
        float a = 0.f;
#pragma unroll
        for (int k = 0; k < K3C; k++)
            a = fmaf(sU[k * NSLOT_F + s], sW[e * K3C + k], a);
        S3g[c * S3_PER_C + idx] = a;
    }

    // S2 packed (s2, 0)
    for (int t = tid; t < S2U_PER_C; t += 512) {
        const int e = t / NPAIR, pp = t - e * NPAIR;
        const int w = g_pw[pp], v = g_pv[pp];
        float s = 0.f;
#pragma unroll
        for (int k = 0; k < K2C; k++) {
            float u = U2[(w * 16 + v) * K2C + k];
            if (w != v) u += U2[(v * 16 + w) * K2C + k];
            s = fmaf(u, W2[(e * K2C + k) * CDIM + c], s);
        }
        S2gu[c * S2U_PER_C + t] = (ull)__float_as_uint(s);  // (s, 0)
    }
    if (tid < V1_PER_C) {
        const int e = tid >> 4, w = tid & 15;
        V1g[c * V1_PER_C + tid] = U1[w] * W1[e * CDIM + c];
    }
}

// ---- sc_main: single-pair dot block (round-3 proven structure) -----------------
template <int N>
__device__ __forceinline__ void dot_block(
    const ull* __restrict__ sS3u, int off, const ull* __restrict__ s2p,
    const ull* __restrict__ sYd, int bg,
    const ull (&xp0)[8], const ull (&xp1)[8], const ull (&xp2)[8], const ull (&xp3)[8],
    ull& ya0, ull& ya1, ull& ya2, ull& ya3)
{
#pragma unroll 1
    for (int e = 0; e < EDIM; e++) {
        const ull* st = sS3u + e * NSLOT_U + off;
        const ull s2 = s2p[e * NPAIR];
        ull d0 = s2, d1 = s2, d2 = s2, d3 = s2;
#pragma unroll
        for (int u = N - 1; u >= 0; u--) {
            const ull t = st[u];
            d0 = fma2(t, xp0[7 - u], d0);
            d1 = fma2(t, xp1[7 - u], d1);
            d2 = fma2(t, xp2[7 - u], d2);
            d3 = fma2(t, xp3[7 - u], d3);
        }
        const ull* yrow = sYd + e * 256;
        ya0 = fma2(d0, yrow[bg], ya0);
        ya1 = fma2(d1, yrow[bg + 64], ya1);
        ya2 = fma2(d2, yrow[bg + 128], ya2);
        ya3 = fma2(d3, yrow[bg + 192], ya3);
    }
}

// Grid (c=256, btile=4). 512 threads: bg = tid&63 owns 4 b's; psplit = tid>>6
// owns one balanced bucket of 17 pairs. Lanes carry (even-i, odd-i).
__global__ __launch_bounds__(512, 1)
void sc_main(const float* __restrict__ x, const float* __restrict__ y,
             float* __restrict__ out) {
    extern __shared__ char smraw[];
    float* sS3 = reinterpret_cast<float*>(smraw);
    ull*   sS2 = reinterpret_cast<ull*>(sS3 + S3_PER_C);
    float* sXs = reinterpret_cast<float*>(sS2 + S2U_PER_C);
    ull*   sYd = reinterpret_cast<ull*>(sXs + 256 * 17);
    int*   sPW = reinterpret_cast<int*>(sYd + EDIM * 256);
    int*   sPV = sPW + NPAIR;
    int*   sOF = sPV + NPAIR;
    int*   sLN = sOF + NPAIR;
    float* red = reinterpret_cast<float*>(sLN + NPAIR);
    const ull* sS3u = reinterpret_cast<const ull*>(sS3);

    const int tid    = threadIdx.x;
    const int c      = blockIdx.x;
    const int base   = blockIdx.y * 256;
    const int bg     = tid & 63;
    const int psplit = tid >> 6;

    // ---- stage S3 / S2 ----
    {
        const float4* src = reinterpret_cast<const float4*>(S3g + c * S3_PER_C);
        float4* dst = reinterpret_cast<float4*>(sS3);
#pragma unroll
        for (int t = 0; t < S3_PER_C / 4 / 512; t++)
            dst[tid + t * 512] = src[tid + t * 512];
        for (int t = tid; t < S2U_PER_C; t += 512)
            sS2[t] = S2gu[c * S2U_PER_C + t];
    }
    // ---- stage x scalars ----
#pragma unroll
    for (int t = 0; t < 8; t++) {
        const int idx = tid + t * 512;            // 4096 = 256*16
        const int b = idx >> 4, i = idx & 15;
        sXs[b * 17 + i] = x[((base + b) * CDIM + c) * LDIM + i];
    }
    // ---- stage dup'd y pairs [e][b] ----
#pragma unroll
    for (int t = 0; t < 5; t++) {
        const int idx = tid + t * 512;            // 2560 = 10*256
        const int b = idx & 255, e = idx >> 8;
        const float yv = y[(base + b) * EDIM + e];
        sYd[e * 256 + b] = pk2(yv, yv);
    }
    if (tid < NPAIR) {
        sPW[tid] = g_pw[tid];
        sPV[tid] = g_pv[tid];
        sOF[tid] = g_off[tid];
        sLN[tid] = g_len[tid];
    }
    __syncthreads();

    // ---- per-thread packed x (4 b's) ----
    const int b0 = bg, b1 = bg + 64, b2 = bg + 128, b3 = bg + 192;
    ull xp0[8], xp1[8], xp2[8], xp3[8];
#pragma unroll
    for (int q = 0; q < 8; q++) {
        xp0[q] = pk2(sXs[b0 * 17 + 2 * q], sXs[b0 * 17 + 2 * q + 1]);
        xp1[q] = pk2(sXs[b1 * 17 + 2 * q], sXs[b1 * 17 + 2 * q + 1]);
        xp2[q] = pk2(sXs[b2 * 17 + 2 * q], sXs[b2 * 17 + 2 * q + 1]);
        xp3[q] = pk2(sXs[b3 * 17 + 2 * q], sXs[b3 * 17 + 2 * q + 1]);
    }

    ull acc0 = 0ull, acc1 = 0ull, acc2 = 0ull, acc3 = 0ull;

#pragma unroll 1
    for (int j = 0; j < PPB; j++) {
        const int p = psplit * PPB + j;
        const int w = sPW[p], v = sPV[p];
        const int off = sOF[p];
        const float P0 = sXs[b0 * 17 + w] * sXs[b0 * 17 + v];
        const float P1 = sXs[b1 * 17 + w] * sXs[b1 * 17 + v];
        const float P2 = sXs[b2 * 17 + w] * sXs[b2 * 17 + v];
        const float P3 = sXs[b3 * 17 + w] * sXs[b3 * 17 + v];
        ull ya0 = 0ull, ya1 = 0ull, ya2 = 0ull, ya3 = 0ull;
        const ull* s2p = sS2 + p;
        switch (sLN[p]) {
            case 8: dot_block<8>(sS3u, off, s2p, sYd, bg, xp0, xp1, xp2, xp3, ya0, ya1, ya2, ya3); break;
            case 7: dot_block<7>(sS3u, off, s2p, sYd, bg, xp0, xp1, xp2, xp3, ya0, ya1, ya2, ya3); break;
            case 6: dot_block<6>(sS3u, off, s2p, sYd, bg, xp0, xp1, xp2, xp3, ya0, ya1, ya2, ya3); break;
            case 5: dot_block<5>(sS3u, off, s2p, sYd, bg, xp0, xp1, xp2, xp3, ya0, ya1, ya2, ya3); break;
            case 4: dot_block<4>(sS3u, off, s2p, sYd, bg, xp0, xp1, xp2, xp3, ya0, ya1, ya2, ya3); break;
            case 3: dot_block<3>(sS3u, off, s2p, sYd, bg, xp0, xp1, xp2, xp3, ya0, ya1, ya2, ya3); break;
            case 2: dot_block<2>(sS3u, off, s2p, sYd, bg, xp0, xp1, xp2, xp3, ya0, ya1, ya2, ya3); break;
            default: dot_block<1>(sS3u, off, s2p, sYd, bg, xp0, xp1, xp2, xp3, ya0, ya1, ya2, ya3); break;
        }
        acc0 = fma2(pk2(P0, P0), ya0, acc0);
        acc1 = fma2(pk2(P1, P1), ya1, acc1);
        acc2 = fma2(pk2(P2, P2), ya2, acc2);
        acc3 = fma2(pk2(P3, P3), ya3, acc3);
    }

    float lo, hi;
    float s0, s1, s2v, s3v;
    upk2(acc0, lo, hi); s0  = lo + hi;
    upk2(acc1, lo, hi); s1  = lo + hi;
    upk2(acc2, lo, hi); s2v = lo + hi;
    upk2(acc3, lo, hi); s3v = lo + hi;

    // ---- nu=1 (psplit 0 only) ----
    if (psplit == 0) {
        const float* v1 = V1g + c * V1_PER_C;
        float add0 = 0.f, add1 = 0.f, add2 = 0.f, add3 = 0.f;
#pragma unroll 1
        for (int e = 0; e < EDIM; e++) {
            float t0 = 0.f, t1 = 0.f, t2 = 0.f, t3 = 0.f;
#pragma unroll
            for (int w = 0; w < 16; w++) {
                const float vv = v1[e * 16 + w];
                t0 = fmaf(vv, sXs[b0 * 17 + w], t0);
                t1 = fmaf(vv, sXs[b1 * 17 + w], t1);
                t2 = fmaf(vv, sXs[b2 * 17 + w], t2);
                t3 = fmaf(vv, sXs[b3 * 17 + w], t3);
            }
            add0 = fmaf(y[(base + b0) * EDIM + e], t0, add0);
            add1 = fmaf(y[(base + b1) * EDIM + e], t1, add1);
            add2 = fmaf(y[(base + b2) * EDIM + e], t2, add2);
            add3 = fmaf(y[(base + b3) * EDIM + e], t3, add3);
        }
        s0 += add0; s1 += add1; s2v += add2; s3v += add3;
    }

    // ---- deterministic cross-split reduction ----
    red[psplit * 256 + b0] = s0;
    red[psplit * 256 + b1] = s1;
    red[psplit * 256 + b2] = s2v;
    red[psplit * 256 + b3] = s3v;
    __syncthreads();
    if (tid < 256) {
        float s = 0.f;
#pragma unroll
        for (int k = 0; k < 8; k++) s += red[k * 256 + tid];
        out[(base + tid) * CDIM + c] = s;
    }
}

// ---- launch --------------------------------------------------------------------
extern "C" void kernel_launch(void* const* d_in, const int* in_sizes, int n_in,
                              void* d_out, int out_size) {
    const float* x  = (const float*)d_in[0];
    const float* y  = (const float*)d_in[1];
    const float* U3 = (const float*)d_in[2];
    const float* U2 = (const float*)d_in[3];
    const float* U1 = (const float*)d_in[4];
    const float* W3 = (const float*)d_in[5];
    const float* W2 = (const float*)d_in[6];
    const float* W1 = (const float*)d_in[7];
    float* out = (float*)d_out;

    cudaFuncSetAttribute(k_s3, cudaFuncAttributeMaxDynamicSharedMemorySize, SMEM_KS3);
    cudaFuncSetAttribute(sc_main, cudaFuncAttributeMaxDynamicSharedMemorySize, SMEM_MAIN);

    k_tab<<<1, 256>>>();
    k_sym<<<(K3C * NSLOT_F + 255) / 256, 256>>>(U3);
    k_s3<<<CDIM, 512, SMEM_KS3>>>(W3, U2, W2, U1, W1);

    dim3 grid(CDIM, BDIM / 256);
    sc_main<<<grid, 512, SMEM_MAIN>>>(x, y, out);
}

// round 6
// speedup vs baseline: 1.5616x; 1.0261x over previous
#include <cuda_runtime.h>
#include <cstdint>

// ---------------------------------------------------------------------------
// out[b,c] = sum_e y[b,e]*( sum_{w<=v<=i} S3[c,e,(w,v,i)] x_w x_v x_i
//                         + sum_{w<=v}    S2[c,e,(w,v)]   x_w x_v
//                         + sum_w         V1[c,e,w]       x_w )
// Round 6: scalar y in smem (1 crossbar cyc vs 2) + register-side lane dup.
// ---------------------------------------------------------------------------

namespace {
constexpr int LDIM = 16;
constexpr int EDIM = 10;
constexpr int CDIM = 256;
constexpr int BDIM = 1024;
constexpr int K3C  = 23;
constexpr int K2C  = 4;

constexpr int NPAIR    = 136;           // (w<=v) pairs, 8 buckets x 17
constexpr int NBUCK    = 8;
constexpr int PPB      = 17;
constexpr int BSTRIDE  = 64;            // ull slots per bucket (max 59 used)
constexpr int NSLOT_U  = NBUCK * BSTRIDE;   // 512 ull per e
constexpr int NSLOT_F  = 2 * NSLOT_U;       // 1024 floats per e

constexpr int S3_PER_C  = EDIM * NSLOT_F;   // 10240 floats
constexpr int S2U_PER_C = EDIM * NPAIR;     // 1360 ull
constexpr int V1_PER_C  = EDIM * LDIM;      // 160

constexpr int SMEM_MAIN =
    S3_PER_C * 4 +        // 40960
    S2U_PER_C * 8 +       // 10880
    256 * 17 * 4 +        // 17408 x scalars, stride 17
    EDIM * 256 * 4 +      // 10240 scalar y [e][b]
    NPAIR * 4 * 4 +       //  2176 tables (w,v,off,len)
    8 * 256 * 4;          //  8192 reduction
// = 89856

constexpr int SMEM_KS3 = (K3C * NSLOT_F + EDIM * K3C + 8) * 4;  // ~95.2 KB
}

// ---- device scratch ----------------------------------------------------------
__device__ int   g_pw[NPAIR], g_pv[NPAIR], g_off[NPAIR], g_len[NPAIR];
__device__ int   g_s2p[NSLOT_F], g_s2i[NSLOT_F];   // float-slot -> pair, i
__device__ float U3symT[K3C * NSLOT_F];            // [k][slot], zero-padded
__device__ float S3g[CDIM * S3_PER_C];             // ~10.5 MB
__device__ unsigned long long S2gu[CDIM * S2U_PER_C];
__device__ float V1g[CDIM * V1_PER_C];

// ---- packed f32x2 helpers (sm_103a) -------------------------------------------
using ull = unsigned long long;
__device__ __forceinline__ ull pk2(float a, float b) {
    ull r;
    asm("mov.b64 %0, {%1, %2};"
        : "=l"(r) : "r"(__float_as_uint(a)), "r"(__float_as_uint(b)));
    return r;
}
// duplicate one scalar into both lanes (single MOV.64 from one 32-bit reg)
__device__ __forceinline__ ull dup2(float a) {
    ull r;
    asm("mov.b64 %0, {%1, %1};" : "=l"(r) : "r"(__float_as_uint(a)));
    return r;
}
__device__ __forceinline__ ull fma2(ull a, ull b, ull c) {
    ull d;
    asm("fma.rn.f32x2 %0, %1, %2, %3;" : "=l"(d) : "l"(a), "l"(b), "l"(c));
    return d;
}
__device__ __forceinline__ void upk2(ull v, float& a, float& b) {
    unsigned int lo, hi;
    asm("mov.b64 {%0, %1}, %2;" : "=r"(lo), "=r"(hi) : "l"(v));
    a = __uint_as_float(lo);
    b = __uint_as_float(hi);
}

// ---- k_tab: parallel table builder, balanced buckets, NO padding --------------
__device__ __forceinline__ int len_of_rank(int r) {
    int o = 0, L = 8;
    while (L > 1 && o + 4 * (8 - L) + 3 <= r) { o += 4 * (8 - L) + 3; L--; }
    return L;
}
__global__ void k_tab() {
    const int tid = threadIdx.x;
    for (int s = tid; s < NSLOT_F; s += 256) { g_s2i[s] = -1; g_s2p[s] = 0; }
    __syncthreads();
    if (tid >= NPAIR) return;

    int p = tid, w = 0;
    while (p >= LDIM - w) { p -= LDIM - w; w++; }
    const int v = w + p;
    const int g = v >> 1;
    const int L = 8 - g;

    int idx = 0;
    for (int w2 = 0; w2 < w; w2++) {
        if (2 * g     >= w2) idx++;
        if (2 * g + 1 >= w2) idx++;
    }
    if ((v & 1) && (2 * g >= w)) idx++;
    int offL = 0;
    for (int L2 = 8; L2 > L; L2--) offL += 4 * (8 - L2) + 3;
    const int rank   = offL + idx;
    const int bucket = rank & 7;
    const int j      = rank >> 3;

    int off_local = 0;
    for (int j2 = 0; j2 < j; j2++)
        off_local += len_of_rank(j2 * 8 + bucket);

    const int off_abs = bucket * BSTRIDE + off_local;
    const int pi = bucket * PPB + j;
    g_pw[pi]  = w;
    g_pv[pi]  = v;
    g_off[pi] = off_abs;
    g_len[pi] = L;

    for (int u = 0; u < L; u++)
        for (int r = 0; r < 2; r++) {
            const int s = 2 * (off_abs + u) + r;
            const int i = 14 - 2 * u + r;
            g_s2p[s] = pi;
            g_s2i[s] = (i >= v) ? i : -1;
        }
}

// ---- k_sym: symmetrized U3, transposed [k][slot] ------------------------------
__device__ __forceinline__ float u3at(const float* U3, int a, int b, int c, int k) {
    return U3[((a * 16 + b) * 16 + c) * K3C + k];
}
__global__ void k_sym(const float* __restrict__ U3) {
    const int idx = blockIdx.x * 256 + threadIdx.x;   // 23 * 1024
    if (idx >= K3C * NSLOT_F) return;
    const int s = idx & (NSLOT_F - 1);
    const int k = idx >> 10;
    const int i = g_s2i[s];
    float val = 0.f;
    if (i >= 0) {
        const int pi = g_s2p[s];
        const int w = g_pw[pi], v = g_pv[pi];
        if (w == v && v == i) {
            val = u3at(U3, w, w, w, k);
        } else if (w == v) {
            val = u3at(U3, w, w, i, k) + u3at(U3, w, i, w, k) + u3at(U3, i, w, w, k);
        } else if (v == i) {
            val = u3at(U3, w, v, v, k) + u3at(U3, v, w, v, k) + u3at(U3, v, v, w, k);
        } else {
            val = u3at(U3, w, v, i, k) + u3at(U3, w, i, v, k) +
                  u3at(U3, v, w, i, k) + u3at(U3, v, i, w, k) +
                  u3at(U3, i, w, v, k) + u3at(U3, i, v, w, k);
        }
    }
    U3symT[k * NSLOT_F + s] = val;
}

// ---- k_s3: per-c contraction + fused S2/V1 ------------------------------------
__global__ __launch_bounds__(512, 1)
void k_s3(const float* __restrict__ W3, const float* __restrict__ U2,
          const float* __restrict__ W2, const float* __restrict__ U1,
          const float* __restrict__ W1) {
    extern __shared__ float sm[];
    float* sU = sm;                       // [23][1024]
    float* sW = sm + K3C * NSLOT_F;       // [10][23]
    const int tid = threadIdx.x;
    const int c   = blockIdx.x;

    for (int t = tid; t < K3C * NSLOT_F; t += 512) sU[t] = U3symT[t];
    if (tid < EDIM * K3C) {
        const int e = tid / K3C, k = tid - e * K3C;
        sW[tid] = W3[(e * K3C + k) * CDIM + c];
    }
    __syncthreads();

#pragma unroll 1
    for (int idx = tid; idx < S3_PER_C; idx += 512) {
        const int e = idx >> 10;
        const int s = idx & (NSLOT_F - 1);
        float a = 0.f;
#pragma unroll
        for (int k = 0; k < K3C; k++)
            a = fmaf(sU[k * NSLOT_F + s], sW[e * K3C + k], a);
        S3g[c * S3_PER_C + idx] = a;
    }

    for (int t = tid; t < S2U_PER_C; t += 512) {
        const int e = t / NPAIR, pp = t - e * NPAIR;
        const int w = g_pw[pp], v = g_pv[pp];
        float s = 0.f;
#pragma unroll
        for (int k = 0; k < K2C; k++) {
            float u = U2[(w * 16 + v) * K2C + k];
            if (w != v) u += U2[(v * 16 + w) * K2C + k];
            s = fmaf(u, W2[(e * K2C + k) * CDIM + c], s);
        }
        S2gu[c * S2U_PER_C + t] = (ull)__float_as_uint(s);  // (s, 0)
    }
    if (tid < V1_PER_C) {
        const int e = tid >> 4, w = tid & 15;
        V1g[c * V1_PER_C + tid] = U1[w] * W1[e * CDIM + c];
    }
}

// ---- sc_main: single-pair dot, scalar-y loads ----------------------------------
template <int N>
__device__ __forceinline__ void dot_block(
    const ull* __restrict__ sS3u, int off, const ull* __restrict__ s2p,
    const float* __restrict__ sYs, int bg,
    const ull (&xp0)[8], const ull (&xp1)[8], const ull (&xp2)[8], const ull (&xp3)[8],
    ull& ya0, ull& ya1, ull& ya2, ull& ya3)
{
#pragma unroll 1
    for (int e = 0; e < EDIM; e++) {
        const ull* st = sS3u + e * NSLOT_U + off;
        const ull s2 = s2p[e * NPAIR];
        ull d0 = s2, d1 = s2, d2 = s2, d3 = s2;
#pragma unroll
        for (int u = N - 1; u >= 0; u--) {
            const ull t = st[u];
            d0 = fma2(t, xp0[7 - u], d0);
            d1 = fma2(t, xp1[7 - u], d1);
            d2 = fma2(t, xp2[7 - u], d2);
            d3 = fma2(t, xp3[7 - u], d3);
        }
        const float* yrow = sYs + e * 256;   // 32 lanes x 4B = 1 crossbar cyc
        ya0 = fma2(d0, dup2(yrow[bg]), ya0);
        ya1 = fma2(d1, dup2(yrow[bg + 64]), ya1);
        ya2 = fma2(d2, dup2(yrow[bg + 128]), ya2);
        ya3 = fma2(d3, dup2(yrow[bg + 192]), ya3);
    }
}

// Grid (c=256, btile=4). 512 threads: bg = tid&63 owns 4 b's; psplit = tid>>6
// owns one balanced bucket of 17 pairs. Lanes carry (even-i, odd-i).
__global__ __launch_bounds__(512, 1)
void sc_main(const float* __restrict__ x, const float* __restrict__ y,
             float* __restrict__ out) {
    extern __shared__ char smraw[];
    float* sS3 = reinterpret_cast<float*>(smraw);
    ull*   sS2 = reinterpret_cast<ull*>(sS3 + S3_PER_C);
    float* sXs = reinterpret_cast<float*>(sS2 + S2U_PER_C);
    float* sYs = sXs + 256 * 17;
    int*   sPW = reinterpret_cast<int*>(sYs + EDIM * 256);
    int*   sPV = sPW + NPAIR;
    int*   sOF = sPV + NPAIR;
    int*   sLN = sOF + NPAIR;
    float* red = reinterpret_cast<float*>(sLN + NPAIR);
    const ull* sS3u = reinterpret_cast<const ull*>(sS3);

    const int tid    = threadIdx.x;
    const int c      = blockIdx.x;
    const int base   = blockIdx.y * 256;
    const int bg     = tid & 63;
    const int psplit = tid >> 6;

    // ---- stage S3 / S2 ----
    {
        const float4* src = reinterpret_cast<const float4*>(S3g + c * S3_PER_C);
        float4* dst = reinterpret_cast<float4*>(sS3);
#pragma unroll
        for (int t = 0; t < S3_PER_C / 4 / 512; t++)
            dst[tid + t * 512] = src[tid + t * 512];
        for (int t = tid; t < S2U_PER_C; t += 512)
            sS2[t] = S2gu[c * S2U_PER_C + t];
    }
    // ---- stage x scalars ----
#pragma unroll
    for (int t = 0; t < 8; t++) {
        const int idx = tid + t * 512;            // 4096 = 256*16
        const int b = idx >> 4, i = idx & 15;
        sXs[b * 17 + i] = x[((base + b) * CDIM + c) * LDIM + i];
    }
    // ---- stage scalar y [e][b] ----
#pragma unroll
    for (int t = 0; t < 5; t++) {
        const int idx = tid + t * 512;            // 2560 = 10*256
        const int b = idx & 255, e = idx >> 8;
        sYs[e * 256 + b] = y[(base + b) * EDIM + e];
    }
    if (tid < NPAIR) {
        sPW[tid] = g_pw[tid];
        sPV[tid] = g_pv[tid];
        sOF[tid] = g_off[tid];
        sLN[tid] = g_len[tid];
    }
    __syncthreads();

    // ---- per-thread packed x (4 b's) ----
    const int b0 = bg, b1 = bg + 64, b2 = bg + 128, b3 = bg + 192;
    ull xp0[8], xp1[8], xp2[8], xp3[8];
#pragma unroll
    for (int q = 0; q < 8; q++) {
        xp0[q] = pk2(sXs[b0 * 17 + 2 * q], sXs[b0 * 17 + 2 * q + 1]);
        xp1[q] = pk2(sXs[b1 * 17 + 2 * q], sXs[b1 * 17 + 2 * q + 1]);
        xp2[q] = pk2(sXs[b2 * 17 + 2 * q], sXs[b2 * 17 + 2 * q + 1]);
        xp3[q] = pk2(sXs[b3 * 17 + 2 * q], sXs[b3 * 17 + 2 * q + 1]);
    }

    ull acc0 = 0ull, acc1 = 0ull, acc2 = 0ull, acc3 = 0ull;

#pragma unroll 1
    for (int j = 0; j < PPB; j++) {
        const int p = psplit * PPB + j;
        const int w = sPW[p], v = sPV[p];
        const int off = sOF[p];
        const float P0 = sXs[b0 * 17 + w] * sXs[b0 * 17 + v];
        const float P1 = sXs[b1 * 17 + w] * sXs[b1 * 17 + v];
        const float P2 = sXs[b2 * 17 + w] * sXs[b2 * 17 + v];
        const float P3 = sXs[b3 * 17 + w] * sXs[b3 * 17 + v];
        ull ya0 = 0ull, ya1 = 0ull, ya2 = 0ull, ya3 = 0ull;
        const ull* s2p = sS2 + p;
        switch (sLN[p]) {
            case 8: dot_block<8>(sS3u, off, s2p, sYs, bg, xp0, xp1, xp2, xp3, ya0, ya1, ya2, ya3); break;
            case 7: dot_block<7>(sS3u, off, s2p, sYs, bg, xp0, xp1, xp2, xp3, ya0, ya1, ya2, ya3); break;
            case 6: dot_block<6>(sS3u, off, s2p, sYs, bg, xp0, xp1, xp2, xp3, ya0, ya1, ya2, ya3); break;
            case 5: dot_block<5>(sS3u, off, s2p, sYs, bg, xp0, xp1, xp2, xp3, ya0, ya1, ya2, ya3); break;
            case 4: dot_block<4>(sS3u, off, s2p, sYs, bg, xp0, xp1, xp2, xp3, ya0, ya1, ya2, ya3); break;
            case 3: dot_block<3>(sS3u, off, s2p, sYs, bg, xp0, xp1, xp2, xp3, ya0, ya1, ya2, ya3); break;
            case 2: dot_block<2>(sS3u, off, s2p, sYs, bg, xp0, xp1, xp2, xp3, ya0, ya1, ya2, ya3); break;
            default: dot_block<1>(sS3u, off, s2p, sYs, bg, xp0, xp1, xp2, xp3, ya0, ya1, ya2, ya3); break;
        }
        acc0 = fma2(dup2(P0), ya0, acc0);
        acc1 = fma2(dup2(P1), ya1, acc1);
        acc2 = fma2(dup2(P2), ya2, acc2);
        acc3 = fma2(dup2(P3), ya3, acc3);
    }

    float lo, hi;
    float s0, s1, s2v, s3v;
    upk2(acc0, lo, hi); s0  = lo + hi;
    upk2(acc1, lo, hi); s1  = lo + hi;
    upk2(acc2, lo, hi); s2v = lo + hi;
    upk2(acc3, lo, hi); s3v = lo + hi;

    // ---- nu=1 (psplit 0 only) ----
    if (psplit == 0) {
        const float* v1 = V1g + c * V1_PER_C;
        float add0 = 0.f, add1 = 0.f, add2 = 0.f, add3 = 0.f;
#pragma unroll 1
        for (int e = 0; e < EDIM; e++) {
            float t0 = 0.f, t1 = 0.f, t2 = 0.f, t3 = 0.f;
#pragma unroll
            for (int w = 0; w < 16; w++) {
                const float vv = v1[e * 16 + w];
                t0 = fmaf(vv, sXs[b0 * 17 + w], t0);
                t1 = fmaf(vv, sXs[b1 * 17 + w], t1);
                t2 = fmaf(vv, sXs[b2 * 17 + w], t2);
                t3 = fmaf(vv, sXs[b3 * 17 + w], t3);
            }
            add0 = fmaf(sYs[e * 256 + b0], t0, add0);
            add1 = fmaf(sYs[e * 256 + b1], t1, add1);
            add2 = fmaf(sYs[e * 256 + b2], t2, add2);
            add3 = fmaf(sYs[e * 256 + b3], t3, add3);
        }
        s0 += add0; s1 += add1; s2v += add2; s3v += add3;
    }

    // ---- deterministic cross-split reduction ----
    red[psplit * 256 + b0] = s0;
    red[psplit * 256 + b1] = s1;
    red[psplit * 256 + b2] = s2v;
    red[psplit * 256 + b3] = s3v;
    __syncthreads();
    if (tid < 256) {
        float s = 0.f;
#pragma unroll
        for (int k = 0; k < 8; k++) s += red[k * 256 + tid];
        out[(base + tid) * CDIM + c] = s;
    }
}

// ---- launch --------------------------------------------------------------------
extern "C" void kernel_launch(void* const* d_in, const int* in_sizes, int n_in,
                              void* d_out, int out_size) {
    const float* x  = (const float*)d_in[0];
    const float* y  = (const float*)d_in[1];
    const float* U3 = (const float*)d_in[2];
    const float* U2 = (const float*)d_in[3];
    const float* U1 = (const float*)d_in[4];
    const float* W3 = (const float*)d_in[5];
    const float* W2 = (const float*)d_in[6];
    const float* W1 = (const float*)d_in[7];
    float* out = (float*)d_out;

    cudaFuncSetAttribute(k_s3, cudaFuncAttributeMaxDynamicSharedMemorySize, SMEM_KS3);
    cudaFuncSetAttribute(sc_main, cudaFuncAttributeMaxDynamicSharedMemorySize, SMEM_MAIN);

    k_tab<<<1, 256>>>();
    k_sym<<<(K3C * NSLOT_F + 255) / 256, 256>>>(U3);
    k_s3<<<CDIM, 512, SMEM_KS3>>>(W3, U2, W2, U1, W1);

    dim3 grid(CDIM, BDIM / 256);
    sc_main<<<grid, 512, SMEM_MAIN>>>(x, y, out);
}